// round 6
// baseline (speedup 1.0000x reference)
#include <cuda_runtime.h>
#include <math.h>

#define Bsz 64
#define Ssz 512
#define Hsz 400
#define Dsz 400
#define Vsz 32000
#define Lsz 16
#define NPART 8          // per-step GEMM K split
#define KC   50          // K per part
#define JT   24          // j-tile per block
#define HC   8           // h chunks in fused kernel
#define HCW  50          // h per chunk

// ---------------- scratch (device globals; no allocation) ----------------
__device__ float g_Gpart[NPART][Bsz][2400];  // per-step partials [p][b][gi|gh]
__device__ float g_hA[Bsz * Hsz];
__device__ float g_hB[Bsz * Hsz];
__device__ float g_x[Bsz * Dsz];
__device__ float g_xB[Lsz * Bsz * Dsz];      // batched inputs (teacher forcing)
__device__ float g_giB[Lsz][Bsz][1200];      // batched gi results
__device__ float g_encT[Bsz][Hsz][Ssz];      // transposed encoder outputs
__device__ float g_scpart[HC][Bsz][Ssz];     // partial scores per h-chunk
__device__ int   g_cnt[Bsz];                 // arrival counters

// ---------------- f32x2 packed-FMA helpers ----------------
__device__ __forceinline__ unsigned long long pk2(float x, float y) {
    unsigned long long r;
    asm("mov.b64 %0, {%1, %2};" : "=l"(r) : "f"(x), "f"(y));
    return r;
}
__device__ __forceinline__ void ffma2(unsigned long long& d,
                                      unsigned long long a, unsigned long long b) {
    asm("fma.rn.f32x2 %0, %1, %2, %0;" : "+l"(d) : "l"(a), "l"(b));
}
__device__ __forceinline__ float2 up2(unsigned long long v) {
    float2 f;
    asm("mov.b64 {%0, %1}, %2;" : "=f"(f.x), "=f"(f.y) : "l"(v));
    return f;
}

// ---------------- zero output with evict-first stores ----------------
__global__ __launch_bounds__(256) void zero_kernel(float* __restrict__ out, int n4, int n) {
    int idx = blockIdx.x * 256 + threadIdx.x;
    int stride = gridDim.x * 256;
    for (int i = idx; i < n4; i += stride) {
        float4* p = (float4*)out + i;
        asm volatile("st.global.cs.v4.f32 [%0], {%1, %2, %3, %4};"
                     :: "l"(p), "f"(0.f), "f"(0.f), "f"(0.f), "f"(0.f) : "memory");
    }
    for (int i = n4 * 4 + idx; i < n; i += stride) {
        asm volatile("st.global.cs.f32 [%0], %1;" :: "l"(out + i), "f"(0.f) : "memory");
    }
}

// ---------------- init ----------------
__global__ void init_kernel(const float* __restrict__ eh,
                            const float* __restrict__ slot_emb,
                            const int* __restrict__ slot_p) {
    int idx = blockIdx.x * blockDim.x + threadIdx.x;
    if (idx < Bsz * Hsz) {
        g_hA[idx] = eh[idx];
        int j = idx % Dsz;
        g_x[idx] = slot_emb[slot_p[0] * Dsz + j];
    }
}

// ---------------- build batched X: row (t,b) = t==0 ? slot_emb[slot] : emb[targets[b][t-1]]
__global__ __launch_bounds__(256) void xbuild_kernel(const float* __restrict__ emb,
                                                     const float* __restrict__ slot_emb,
                                                     const int* __restrict__ slot_p,
                                                     const int* __restrict__ targets) {
    int i = blockIdx.x * 256 + threadIdx.x;      // over 1024 rows * 100 float4
    if (i >= Lsz * Bsz * 100) return;
    int row = i / 100, q = i % 100;
    int t = row / Bsz, b = row % Bsz;
    const float* src = (t == 0) ? (slot_emb + slot_p[0] * Dsz)
                                : (emb + (size_t)targets[b * Lsz + (t - 1)] * Dsz);
    ((float4*)(g_xB + (size_t)row * Dsz))[q] = ((const float4*)src)[q];
}

// ---------------- batched gi GEMM: g_giB[t][b][:] = xB[t,b] @ W_ih^T ----------------
// grid = 16 t * 50 jtiles = 800 blocks, 96 threads, full K=400 in 4 tiles of 100.
__global__ __launch_bounds__(96) void batch_gemm_kernel(const float* __restrict__ Wih) {
    __shared__ float As[100][68];
    __shared__ float Ws[100][28];

    int bx = blockIdx.x;
    int bt = bx / 50;
    int jbase = (bx % 50) * JT;
    const float* A = g_xB + (size_t)bt * Bsz * Dsz;

    int tid = threadIdx.x;
    int tj = tid / 16;
    int tb = tid % 16;
    int b0 = 4 * tb;
    int j0 = 4 * tj;

    unsigned long long acc[4][2];
    #pragma unroll
    for (int jj = 0; jj < 4; jj++) { acc[jj][0] = 0ULL; acc[jj][1] = 0ULL; }

    for (int kt = 0; kt < 4; kt++) {
        int kbase = kt * 100;
        for (int i = tid; i < 1600; i += 96) {
            int q = i / 64, b = i % 64;
            float4 v = *(const float4*)&A[b * 400 + kbase + 4 * q];
            As[4 * q + 0][b] = v.x;
            As[4 * q + 1][b] = v.y;
            As[4 * q + 2][b] = v.z;
            As[4 * q + 3][b] = v.w;
        }
        for (int i = tid; i < 600; i += 96) {
            int q = i / 24, j = i % 24;
            float4 v = *(const float4*)&Wih[(jbase + j) * 400 + kbase + 4 * q];
            Ws[4 * q + 0][j] = v.x;
            Ws[4 * q + 1][j] = v.y;
            Ws[4 * q + 2][j] = v.z;
            Ws[4 * q + 3][j] = v.w;
        }
        __syncthreads();
        #pragma unroll 4
        for (int k = 0; k < 100; k++) {
            float4 av = *(const float4*)&As[k][b0];
            float4 wv = *(const float4*)&Ws[k][j0];
            unsigned long long a01 = pk2(av.x, av.y);
            unsigned long long a23 = pk2(av.z, av.w);
            unsigned long long w0 = pk2(wv.x, wv.x);
            unsigned long long w1 = pk2(wv.y, wv.y);
            unsigned long long w2 = pk2(wv.z, wv.z);
            unsigned long long w3 = pk2(wv.w, wv.w);
            ffma2(acc[0][0], a01, w0); ffma2(acc[0][1], a23, w0);
            ffma2(acc[1][0], a01, w1); ffma2(acc[1][1], a23, w1);
            ffma2(acc[2][0], a01, w2); ffma2(acc[2][1], a23, w2);
            ffma2(acc[3][0], a01, w3); ffma2(acc[3][1], a23, w3);
        }
        __syncthreads();
    }

    float val[4][4];
    #pragma unroll
    for (int jj = 0; jj < 4; jj++) {
        float2 lo = up2(acc[jj][0]);
        float2 hi = up2(acc[jj][1]);
        val[jj][0] = lo.x; val[jj][1] = lo.y; val[jj][2] = hi.x; val[jj][3] = hi.y;
    }
    #pragma unroll
    for (int bb = 0; bb < 4; bb++) {
        float4 o = make_float4(val[0][bb], val[1][bb], val[2][bb], val[3][bb]);
        *(float4*)&g_giB[bt][b0 + bb][jbase + j0] = o;
    }
}

// ---------------- transpose enc[b][s][h] -> encT[b][h][s] ----------------
__global__ __launch_bounds__(256) void transpose_kernel(const float* __restrict__ enc) {
    __shared__ float tile[32][33];
    int b  = blockIdx.z;
    int s0 = blockIdx.x * 32;
    int h0 = blockIdx.y * 32;
    int tx = threadIdx.x, ty = threadIdx.y;   // 32 x 8

    #pragma unroll
    for (int i = 0; i < 32; i += 8) {
        int s = s0 + ty + i, h = h0 + tx;
        if (h < Hsz)
            tile[ty + i][tx] = enc[((size_t)b * Ssz + s) * Hsz + h];
    }
    __syncthreads();
    #pragma unroll
    for (int i = 0; i < 32; i += 8) {
        int h = h0 + ty + i, s = s0 + tx;
        if (h < Hsz)
            g_encT[b][h][s] = tile[tx][ty + i];
    }
}

// ---------------- per-step GEMM partials (h half; gi half only when !tf) --------
// grid = 2 mats * 50 jtiles * 8 ksplits = 800 blocks, 96 threads, KC=50.
__global__ __launch_bounds__(96) void gemm_kernel(const float* __restrict__ Wih,
                                                  const float* __restrict__ Whh,
                                                  const int* __restrict__ use_tf_p,
                                                  int t) {
    __shared__ float As[KC][68];
    __shared__ float Ws[KC][28];

    int bx = blockIdx.x;
    int mat = bx / 400;
    int rem = bx % 400;
    int jt  = rem / NPART;
    int ks  = rem % NPART;
    int jbase = jt * JT;
    int kbase = ks * KC;

    if (mat == 0 && use_tf_p[0]) return;   // gi precomputed in batch when tf

    const float* hin = (t & 1) ? g_hB : g_hA;
    const float* A = mat ? hin : g_x;
    const float* W = mat ? Whh : Wih;

    int tid = threadIdx.x;

    // stage via float2 (kbase*4 = 200B offset is 8B-aligned only)
    for (int i = tid; i < 64 * (KC / 2); i += 96) {   // 1600
        int q = i / 64, b = i % 64;
        float2 v = *(const float2*)&A[b * 400 + kbase + 2 * q];
        As[2 * q + 0][b] = v.x;
        As[2 * q + 1][b] = v.y;
    }
    for (int i = tid; i < JT * (KC / 2); i += 96) {   // 600
        int q = i / JT, j = i % JT;
        float2 v = *(const float2*)&W[(jbase + j) * 400 + kbase + 2 * q];
        Ws[2 * q + 0][j] = v.x;
        Ws[2 * q + 1][j] = v.y;
    }
    __syncthreads();

    int tj = tid / 16;
    int tb = tid % 16;
    int b0 = 4 * tb;
    int j0 = 4 * tj;

    unsigned long long acc[4][2];
    #pragma unroll
    for (int jj = 0; jj < 4; jj++) { acc[jj][0] = 0ULL; acc[jj][1] = 0ULL; }

    #pragma unroll 5
    for (int k = 0; k < KC; k++) {
        float4 av = *(const float4*)&As[k][b0];
        float4 wv = *(const float4*)&Ws[k][j0];
        unsigned long long a01 = pk2(av.x, av.y);
        unsigned long long a23 = pk2(av.z, av.w);
        unsigned long long w0 = pk2(wv.x, wv.x);
        unsigned long long w1 = pk2(wv.y, wv.y);
        unsigned long long w2 = pk2(wv.z, wv.z);
        unsigned long long w3 = pk2(wv.w, wv.w);
        ffma2(acc[0][0], a01, w0); ffma2(acc[0][1], a23, w0);
        ffma2(acc[1][0], a01, w1); ffma2(acc[1][1], a23, w1);
        ffma2(acc[2][0], a01, w2); ffma2(acc[2][1], a23, w2);
        ffma2(acc[3][0], a01, w3); ffma2(acc[3][1], a23, w3);
    }

    float val[4][4];
    #pragma unroll
    for (int jj = 0; jj < 4; jj++) {
        float2 lo = up2(acc[jj][0]);
        float2 hi = up2(acc[jj][1]);
        val[jj][0] = lo.x; val[jj][1] = lo.y; val[jj][2] = hi.x; val[jj][3] = hi.y;
    }
    int obase = mat * 1200 + jbase + j0;
    #pragma unroll
    for (int bb = 0; bb < 4; bb++) {
        float4 o = make_float4(val[0][bb], val[1][bb], val[2][bb], val[3][bb]);
        *(float4*)&g_Gpart[ks][b0 + bb][obase] = o;
    }
}

// ---------------- fused gates(h-chunk) + broadcast-MAC scores + tail ----------
// grid = 512 (64 b x 8 h-chunks of 50), 128 threads.
__global__ __launch_bounds__(128) void fused_kernel(const int* __restrict__ lens,
                                                    const int* __restrict__ uttrs,
                                                    const int* __restrict__ targets,
                                                    const int* __restrict__ use_tf_p,
                                                    const float* __restrict__ embedding,
                                                    const float* __restrict__ bih,
                                                    const float* __restrict__ bhh,
                                                    float* __restrict__ out,
                                                    int t, int write_preds) {
    __shared__ float sh[HCW];
    __shared__ float redv[128];
    __shared__ int   redi[128];
    __shared__ int   sh_last;
    __shared__ int   sh_nxt;

    int bx = blockIdx.x;
    int b  = bx >> 3;
    int hc = bx & 7;
    int tid = threadIdx.x;
    int tf = use_tf_p[0];

    const float* hin  = (t & 1) ? g_hB : g_hA;
    float*       hout = (t & 1) ? g_hA : g_hB;

    // ---- gates: block owns h in [hc*50, hc*50+50) ----
    if (tid < HCW) {
        int j = hc * HCW + tid;
        float ir = bih[j], iz = bih[400 + j], in_ = bih[800 + j];
        float hr = bhh[j], hz = bhh[400 + j], hn = bhh[800 + j];
        if (tf) {
            ir += g_giB[t][b][j];
            iz += g_giB[t][b][400 + j];
            in_ += g_giB[t][b][800 + j];
            #pragma unroll
            for (int p = 0; p < NPART; p++) {
                const float* P = &g_Gpart[p][b][0];
                hr += P[1200 + j]; hz += P[1600 + j]; hn += P[2000 + j];
            }
        } else {
            #pragma unroll
            for (int p = 0; p < NPART; p++) {
                const float* P = &g_Gpart[p][b][0];
                ir += P[j];        iz += P[400 + j];  in_ += P[800 + j];
                hr += P[1200 + j]; hz += P[1600 + j]; hn += P[2000 + j];
            }
        }
        float r = 1.f / (1.f + expf(-(ir + hr)));
        float z = 1.f / (1.f + expf(-(iz + hz)));
        float n = tanhf(in_ + r * hn);
        float hnew = (1.f - z) * n + z * hin[b * 400 + j];
        sh[tid] = hnew;
        hout[b * 400 + j] = hnew;
    }
    __syncthreads();

    // ---- partial scores: thread owns 4 s, broadcast-MAC over 50 h ----
    int len = lens[b];
    int s0 = 4 * tid;
    if (s0 < len) {
        const float4* ep = (const float4*)&g_encT[b][hc * HCW][0] + tid;
        float4 acc = make_float4(0.f, 0.f, 0.f, 0.f);
        #pragma unroll 10
        for (int h = 0; h < HCW; h++) {
            float hv = sh[h];
            float4 e = ep[(size_t)h * 128];
            acc.x += e.x * hv; acc.y += e.y * hv;
            acc.z += e.z * hv; acc.w += e.w * hv;
        }
        *(float4*)&g_scpart[hc][b][s0] = acc;
    }

    // ---- last-block-per-b tail ----
    __threadfence();
    __syncthreads();
    if (tid == 0) {
        int old = atomicAdd(&g_cnt[b], 1);
        sh_last = (old == HC - 1);
    }
    __syncthreads();
    if (!sh_last) return;
    __threadfence();
    if (tid == 0) g_cnt[b] = 0;

    float v[4];
    #pragma unroll
    for (int q = 0; q < 4; q++) {
        int s = tid + 128 * q;
        if (s < len) {
            float sum = 0.f;
            #pragma unroll
            for (int p = 0; p < HC; p++) sum += g_scpart[p][b][s];
            v[q] = sum;
        } else {
            v[q] = -INFINITY;
        }
    }

    float mv = v[0]; int mi = tid;
    #pragma unroll
    for (int q = 1; q < 4; q++) {
        if (v[q] > mv) { mv = v[q]; mi = tid + 128 * q; }
    }
    redv[tid] = mv;
    redi[tid] = mi;
    __syncthreads();
    for (int st = 64; st > 0; st >>= 1) {
        if (tid < st) {
            float w2 = redv[tid + st];
            int   i2 = redi[tid + st];
            if (w2 > redv[tid] || (w2 == redv[tid] && i2 < redi[tid])) {
                redv[tid] = w2;
                redi[tid] = i2;
            }
        }
        __syncthreads();
    }
    float m = redv[0];
    int amax = redi[0];
    __syncthreads();

    float e[4], lsum = 0.f;
    #pragma unroll
    for (int q = 0; q < 4; q++) {
        e[q] = expf(v[q] - m);
        lsum += e[q];
    }
    redv[tid] = lsum;
    __syncthreads();
    for (int st = 64; st > 0; st >>= 1) {
        if (tid < st) redv[tid] += redv[tid + st];
        __syncthreads();
    }
    float inv = 1.f / redv[0];

    float* orow = out + (size_t)b * Lsz * Vsz + (size_t)t * Vsz;
    #pragma unroll
    for (int q = 0; q < 4; q++) {
        int s = tid + 128 * q;
        if (s < len)
            atomicAdd(&orow[uttrs[b * Ssz + s]], e[q] * inv);
    }

    if (tid == 0) {
        int pred = uttrs[b * Ssz + amax];
        if (write_preds)
            out[(size_t)Bsz * Lsz * Vsz + (size_t)t * Bsz + b] = (float)pred;
        sh_nxt = tf ? targets[b * Lsz + t] : pred;
    }
    __syncthreads();

    if (tid < 100) {
        ((float4*)(g_x + b * Dsz))[tid] =
            ((const float4*)(embedding + (size_t)sh_nxt * Dsz))[tid];
    }
}

// ---------------- launch ----------------
extern "C" void kernel_launch(void* const* d_in, const int* in_sizes, int n_in,
                              void* d_out, int out_size) {
    const float* eh       = (const float*)d_in[0];
    const float* enc      = (const float*)d_in[1];
    const int*   lens     = (const int*)d_in[2];
    const int*   uttrs    = (const int*)d_in[3];
    const int*   targets  = (const int*)d_in[4];
    const int*   slot     = (const int*)d_in[5];
    const int*   use_tf   = (const int*)d_in[6];
    const float* emb      = (const float*)d_in[7];
    const float* slot_emb = (const float*)d_in[8];
    const float* Wih      = (const float*)d_in[9];
    const float* Whh      = (const float*)d_in[10];
    const float* bih      = (const float*)d_in[11];
    const float* bhh      = (const float*)d_in[12];
    float* out = (float*)d_out;

    zero_kernel<<<1184, 256>>>(out, out_size / 4, out_size);
    init_kernel<<<50, 512>>>(eh, slot_emb, slot);
    xbuild_kernel<<<(Lsz * Bsz * 100 + 255) / 256, 256>>>(emb, slot_emb, slot, targets);
    batch_gemm_kernel<<<800, 96>>>(Wih);
    {
        dim3 tgrid(Ssz / 32, (Hsz + 31) / 32, Bsz);
        dim3 tblk(32, 8);
        transpose_kernel<<<tgrid, tblk>>>(enc);
    }

    int write_preds = out_size > Bsz * Lsz * Vsz;
    for (int t = 0; t < Lsz; t++) {
        gemm_kernel<<<800, 96>>>(Wih, Whh, use_tf, t);
        fused_kernel<<<512, 128>>>(lens, uttrs, targets, use_tf, emb,
                                   bih, bhh, out, t, write_preds);
    }
}

// round 7
// speedup vs baseline: 1.2177x; 1.2177x over previous
#include <cuda_runtime.h>
#include <math.h>

#define Bsz 64
#define Ssz 512
#define Hsz 400
#define Vsz 32000
#define Lsz 16
#define NPART 8
#define KC   50
#define JT   24
#define HC   8
#define HCW  50
#define NBLK 912          // 400 gemm-role + 512 fused-role
#define NTHR 128
#define GEMM_BLOCKS 400
#define BATCH_BLOCKS 480  // 16 t x 30 jtiles (JT_B = 40)

// ---------------- device globals (no allocation) ----------------
__device__ float g_Gpart[NPART][Bsz][2400];
__device__ float g_hA[Bsz * Hsz];
__device__ float g_hB[Bsz * Hsz];
__device__ float g_x[Bsz * Hsz];
__device__ float g_xB[Lsz * Bsz * Hsz];
__device__ float g_giB[Lsz][Bsz][1200];
__device__ float g_encT[Bsz][Hsz][Ssz];
__device__ float g_scpart[2][HC][Bsz][Ssz];
__device__ int   g_cnt[2][Bsz];
__device__ int   g_gemmCnt[Lsz];
__device__ int   g_hCnt[Lsz];
__device__ int   g_fusedCnt[Lsz];
__device__ int   g_bar[2];

// ---------------- f32x2 helpers ----------------
__device__ __forceinline__ unsigned long long pk2(float x, float y) {
    unsigned long long r;
    asm("mov.b64 %0, {%1, %2};" : "=l"(r) : "f"(x), "f"(y));
    return r;
}
__device__ __forceinline__ void ffma2(unsigned long long& d,
                                      unsigned long long a, unsigned long long b) {
    asm("fma.rn.f32x2 %0, %1, %2, %0;" : "+l"(d) : "l"(a), "l"(b));
}
__device__ __forceinline__ float2 up2(unsigned long long v) {
    float2 f;
    asm("mov.b64 {%0, %1}, %2;" : "=f"(f.x), "=f"(f.y) : "l"(v));
    return f;
}

// ---------------- sync primitives ----------------
__device__ __forceinline__ void block_wait(int* cnt, int target) {
    if (threadIdx.x == 0) {
        int v;
        while (true) {
            asm volatile("ld.acquire.gpu.b32 %0, [%1];" : "=r"(v) : "l"(cnt) : "memory");
            if (v >= target) break;
            __nanosleep(128);
        }
    }
    __syncthreads();
}
__device__ __forceinline__ void block_arrive(int* cnt) {
    __threadfence();
    __syncthreads();
    if (threadIdx.x == 0) atomicAdd(cnt, 1);
}

// ---------------- reset counters each replay ----------------
__global__ __launch_bounds__(128) void reset_kernel() {
    int i = threadIdx.x;
    if (i < Lsz) { g_gemmCnt[i] = 0; g_hCnt[i] = 0; g_fusedCnt[i] = 0; }
    if (i < 2) g_bar[i] = 0;
    if (i < Bsz) { g_cnt[0][i] = 0; g_cnt[1][i] = 0; }
}

// ---------------- the persistent kernel ----------------
__global__ __launch_bounds__(NTHR, 8) void persist_kernel(
    const float* __restrict__ eh,
    const float* __restrict__ enc,
    const int* __restrict__ lens,
    const int* __restrict__ uttrs,
    const int* __restrict__ targets,
    const int* __restrict__ slot_p,
    const int* __restrict__ use_tf_p,
    const float* __restrict__ emb,
    const float* __restrict__ slot_emb,
    const float* __restrict__ Wih,
    const float* __restrict__ Whh,
    const float* __restrict__ bih,
    const float* __restrict__ bhh,
    float* __restrict__ out,
    int out_size, int write_preds)
{
    __shared__ float pool[5600];   // 22.4 KB, aliased per phase

    int bx = blockIdx.x;
    int tid = threadIdx.x;
    int gidx = bx * NTHR + tid;
    const int nt = NBLK * NTHR;

    // ============ Phase 0: zero out, init h/x, xbuild, transpose ============
    {
        int n4 = out_size / 4;
        float4* o4 = (float4*)out;
        for (int i = gidx; i < n4; i += nt) {
            float4* p = o4 + i;
            asm volatile("st.global.cs.v4.f32 [%0], {%1, %2, %3, %4};"
                         :: "l"(p), "f"(0.f), "f"(0.f), "f"(0.f), "f"(0.f) : "memory");
        }
        for (int i = n4 * 4 + gidx; i < out_size; i += nt)
            asm volatile("st.global.cs.f32 [%0], %1;" :: "l"(out + i), "f"(0.f) : "memory");

        int slot = slot_p[0];
        for (int i = gidx; i < Bsz * Hsz; i += nt) {
            g_hA[i] = eh[i];
            g_x[i] = slot_emb[slot * Hsz + i % Hsz];
        }
        // xbuild: 16*64 rows x 100 float4
        for (int i = gidx; i < Lsz * Bsz * 100; i += nt) {
            int row = i / 100, q = i % 100;
            int t = row >> 6, b = row & 63;
            const float* src = (t == 0) ? (slot_emb + slot * Hsz)
                                        : (emb + (size_t)targets[b * Lsz + (t - 1)] * Hsz);
            ((float4*)(g_xB + (size_t)row * Hsz))[q] = ((const float4*)src)[q];
        }
        // transpose enc[b][s][h] -> encT[b][h][s], 32x32 tiles
        float (*tile)[33] = (float(*)[33])pool;
        int tx = tid & 31, ty = tid >> 5;    // 32 x 4
        for (int tt = bx; tt < Bsz * 16 * 13; tt += NBLK) {
            int b = tt / (16 * 13);
            int rem = tt % (16 * 13);
            int s0 = (rem / 13) * 32;
            int h0 = (rem % 13) * 32;
            __syncthreads();
            #pragma unroll
            for (int i = 0; i < 32; i += 4) {
                int s = s0 + ty + i, h = h0 + tx;
                if (h < Hsz)
                    tile[ty + i][tx] = enc[((size_t)b * Ssz + s) * Hsz + h];
            }
            __syncthreads();
            #pragma unroll
            for (int i = 0; i < 32; i += 4) {
                int h = h0 + ty + i, s = s0 + tx;
                if (h < Hsz)
                    g_encT[b][h][s] = tile[tx][ty + i];
            }
        }
    }
    block_arrive(&g_bar[0]);
    block_wait(&g_bar[0], NBLK);

    // ============ Phase 1: batch gi GEMM (blocks 0..479) ============
    if (bx < BATCH_BLOCKS) {
        float (*As)[68] = (float(*)[68])pool;              // 50 x 68
        float (*Ws)[44] = (float(*)[44])(pool + 3400);     // 50 x 44
        int bt = bx / 30;
        int jbase = (bx % 30) * 40;
        const float* A = g_xB + (size_t)bt * Bsz * Hsz;

        int tj = tid / 8;      // 0..15 (only 0..9 compute)
        int tb = tid % 8;
        int b0 = 8 * tb;
        int j0 = 4 * tj;
        bool active = (tj < 10);

        unsigned long long acc[4][4];
        #pragma unroll
        for (int j = 0; j < 4; j++)
            #pragma unroll
            for (int p = 0; p < 4; p++) acc[j][p] = 0ULL;

        for (int kt = 0; kt < 8; kt++) {
            int kbase = kt * KC;
            __syncthreads();
            for (int i = tid; i < 1600; i += NTHR) {
                int q = i >> 6, b = i & 63;
                float2 v = *(const float2*)&A[b * Hsz + kbase + 2 * q];
                As[2 * q + 0][b] = v.x;
                As[2 * q + 1][b] = v.y;
            }
            for (int i = tid; i < 1000; i += NTHR) {
                int q = i / 40, j = i % 40;
                float2 v = *(const float2*)&Wih[(size_t)(jbase + j) * Hsz + kbase + 2 * q];
                Ws[2 * q + 0][j] = v.x;
                Ws[2 * q + 1][j] = v.y;
            }
            __syncthreads();
            if (active) {
                #pragma unroll 5
                for (int k = 0; k < KC; k++) {
                    float4 av0 = *(const float4*)&As[k][b0];
                    float4 av1 = *(const float4*)&As[k][b0 + 4];
                    float4 wv  = *(const float4*)&Ws[k][j0];
                    unsigned long long a01 = pk2(av0.x, av0.y);
                    unsigned long long a23 = pk2(av0.z, av0.w);
                    unsigned long long a45 = pk2(av1.x, av1.y);
                    unsigned long long a67 = pk2(av1.z, av1.w);
                    unsigned long long w0 = pk2(wv.x, wv.x);
                    unsigned long long w1 = pk2(wv.y, wv.y);
                    unsigned long long w2 = pk2(wv.z, wv.z);
                    unsigned long long w3 = pk2(wv.w, wv.w);
                    ffma2(acc[0][0], a01, w0); ffma2(acc[0][1], a23, w0);
                    ffma2(acc[0][2], a45, w0); ffma2(acc[0][3], a67, w0);
                    ffma2(acc[1][0], a01, w1); ffma2(acc[1][1], a23, w1);
                    ffma2(acc[1][2], a45, w1); ffma2(acc[1][3], a67, w1);
                    ffma2(acc[2][0], a01, w2); ffma2(acc[2][1], a23, w2);
                    ffma2(acc[2][2], a45, w2); ffma2(acc[2][3], a67, w2);
                    ffma2(acc[3][0], a01, w3); ffma2(acc[3][1], a23, w3);
                    ffma2(acc[3][2], a45, w3); ffma2(acc[3][3], a67, w3);
                }
            }
        }
        if (active) {
            #pragma unroll
            for (int p = 0; p < 4; p++) {
                float2 f0 = up2(acc[0][p]);
                float2 f1 = up2(acc[1][p]);
                float2 f2 = up2(acc[2][p]);
                float2 f3 = up2(acc[3][p]);
                *(float4*)&g_giB[bt][b0 + 2 * p][jbase + j0]     = make_float4(f0.x, f1.x, f2.x, f3.x);
                *(float4*)&g_giB[bt][b0 + 2 * p + 1][jbase + j0] = make_float4(f0.y, f1.y, f2.y, f3.y);
            }
        }
    }
    block_arrive(&g_bar[1]);
    block_wait(&g_bar[1], NBLK);

    int tf = use_tf_p[0];

    // ============ Phase 2: the 16-step recurrence ============
    if (bx < GEMM_BLOCKS) {
        // -------- GEMM role: gh (and gi when !tf) partials --------
        float (*As)[68] = (float(*)[68])pool;              // 50 x 68
        float (*Ws)[28] = (float(*)[28])(pool + 3400);     // 50 x 28
        int jt = bx >> 3, ks = bx & 7;
        int jbase = jt * JT;
        int kbase = ks * KC;
        int tj = tid / 16;     // 0..7 (only 0..5 compute)
        int tb = tid % 16;
        int b0 = 4 * tb;
        int j0 = 4 * tj;
        bool active = (tj < 6);

        for (int t = 0; t < Lsz; t++) {
            if (t > 0) {
                if (tf) block_wait(&g_hCnt[t - 1], 512);
                else    block_wait(&g_fusedCnt[t - 1], 512);
            }
            const float* hin = (t & 1) ? g_hB : g_hA;
            for (int mat = tf ? 1 : 0; mat < 2; mat++) {
                const float* A = mat ? hin : g_x;
                const float* W = mat ? Whh : Wih;
                __syncthreads();
                for (int i = tid; i < 1600; i += NTHR) {
                    int q = i >> 6, b = i & 63;
                    float2 v = *(const float2*)&A[b * Hsz + kbase + 2 * q];
                    As[2 * q + 0][b] = v.x;
                    As[2 * q + 1][b] = v.y;
                }
                for (int i = tid; i < 600; i += NTHR) {
                    int q = i / JT, j = i % JT;
                    float2 v = *(const float2*)&W[(size_t)(jbase + j) * Hsz + kbase + 2 * q];
                    Ws[2 * q + 0][j] = v.x;
                    Ws[2 * q + 1][j] = v.y;
                }
                __syncthreads();
                if (active) {
                    unsigned long long acc[4][2];
                    #pragma unroll
                    for (int jj = 0; jj < 4; jj++) { acc[jj][0] = 0ULL; acc[jj][1] = 0ULL; }
                    #pragma unroll 5
                    for (int k = 0; k < KC; k++) {
                        float4 av = *(const float4*)&As[k][b0];
                        float4 wv = *(const float4*)&Ws[k][j0];
                        unsigned long long a01 = pk2(av.x, av.y);
                        unsigned long long a23 = pk2(av.z, av.w);
                        unsigned long long w0 = pk2(wv.x, wv.x);
                        unsigned long long w1 = pk2(wv.y, wv.y);
                        unsigned long long w2 = pk2(wv.z, wv.z);
                        unsigned long long w3 = pk2(wv.w, wv.w);
                        ffma2(acc[0][0], a01, w0); ffma2(acc[0][1], a23, w0);
                        ffma2(acc[1][0], a01, w1); ffma2(acc[1][1], a23, w1);
                        ffma2(acc[2][0], a01, w2); ffma2(acc[2][1], a23, w2);
                        ffma2(acc[3][0], a01, w3); ffma2(acc[3][1], a23, w3);
                    }
                    int obase = mat * 1200 + jbase + j0;
                    #pragma unroll
                    for (int bb = 0; bb < 4; bb++) {
                        float v0 = (bb & 1) ? up2(acc[0][bb >> 1]).y : up2(acc[0][bb >> 1]).x;
                        float v1 = (bb & 1) ? up2(acc[1][bb >> 1]).y : up2(acc[1][bb >> 1]).x;
                        float v2 = (bb & 1) ? up2(acc[2][bb >> 1]).y : up2(acc[2][bb >> 1]).x;
                        float v3 = (bb & 1) ? up2(acc[3][bb >> 1]).y : up2(acc[3][bb >> 1]).x;
                        *(float4*)&g_Gpart[ks][b0 + bb][obase] = make_float4(v0, v1, v2, v3);
                    }
                }
            }
            block_arrive(&g_gemmCnt[t]);
        }
    } else {
        // -------- fused role: gates + scores + tail --------
        float* sh   = pool;                 // 50
        float* redv = pool + 64;            // 128
        int*   redi = (int*)(pool + 192);   // 128
        float* flg  = pool + 320;           // [0]=last flag, [1]=nxt token

        int fb = bx - GEMM_BLOCKS;
        int b  = fb >> 3;
        int hc = fb & 7;
        int len = lens[b];

        for (int t = 0; t < Lsz; t++) {
            int par = t & 1;
            if (t >= 2) block_wait(&g_fusedCnt[t - 2], 512);
            block_wait(&g_gemmCnt[t], GEMM_BLOCKS);

            const float* hin  = (t & 1) ? g_hB : g_hA;
            float*       hout = (t & 1) ? g_hA : g_hB;

            // gates for h in [hc*50, hc*50+50)
            if (tid < HCW) {
                int j = hc * HCW + tid;
                float ir = bih[j], iz = bih[400 + j], in_ = bih[800 + j];
                float hr = bhh[j], hz = bhh[400 + j], hn = bhh[800 + j];
                if (tf) {
                    ir += g_giB[t][b][j];
                    iz += g_giB[t][b][400 + j];
                    in_ += g_giB[t][b][800 + j];
                    #pragma unroll
                    for (int p = 0; p < NPART; p++) {
                        const float* P = &g_Gpart[p][b][0];
                        hr += P[1200 + j]; hz += P[1600 + j]; hn += P[2000 + j];
                    }
                } else {
                    #pragma unroll
                    for (int p = 0; p < NPART; p++) {
                        const float* P = &g_Gpart[p][b][0];
                        ir += P[j];        iz += P[400 + j];  in_ += P[800 + j];
                        hr += P[1200 + j]; hz += P[1600 + j]; hn += P[2000 + j];
                    }
                }
                float r = 1.f / (1.f + expf(-(ir + hr)));
                float z = 1.f / (1.f + expf(-(iz + hz)));
                float n = tanhf(in_ + r * hn);
                float hnew = (1.f - z) * n + z * hin[b * Hsz + j];
                sh[tid] = hnew;
                hout[b * Hsz + j] = hnew;
            }
            block_arrive(&g_hCnt[t]);      // frees gemm(t+1); also syncs sh

            // partial scores: thread owns 4 s, broadcast-MAC over 50 h
            int s0 = 4 * tid;
            if (s0 < len) {
                const float4* ep = (const float4*)&g_encT[b][hc * HCW][0] + tid;
                float4 acc = make_float4(0.f, 0.f, 0.f, 0.f);
                #pragma unroll 10
                for (int h = 0; h < HCW; h++) {
                    float hv = sh[h];
                    float4 e = ep[(size_t)h * 128];
                    acc.x += e.x * hv; acc.y += e.y * hv;
                    acc.z += e.z * hv; acc.w += e.w * hv;
                }
                *(float4*)&g_scpart[par][hc][b][s0] = acc;
            }

            // arrival on per-b counter (parity slot)
            __threadfence();
            __syncthreads();
            if (tid == 0) {
                int old = atomicAdd(&g_cnt[par][b], 1);
                flg[0] = (old == HC - 1) ? 1.f : 0.f;
            }
            __syncthreads();
            bool last = (flg[0] != 0.f);
            if (!last) {
                block_arrive(&g_fusedCnt[t]);
                continue;
            }

            // ---- tail: softmax + scatter + pred + next x ----
            __threadfence();
            if (tid == 0) g_cnt[par][b] = 0;

            float v[4];
            #pragma unroll
            for (int q = 0; q < 4; q++) {
                int s = tid + 128 * q;
                if (s < len) {
                    float sum = 0.f;
                    #pragma unroll
                    for (int p = 0; p < HC; p++) sum += g_scpart[par][p][b][s];
                    v[q] = sum;
                } else {
                    v[q] = -INFINITY;
                }
            }
            float mv = v[0]; int mi = tid;
            #pragma unroll
            for (int q = 1; q < 4; q++)
                if (v[q] > mv) { mv = v[q]; mi = tid + 128 * q; }
            redv[tid] = mv;
            redi[tid] = mi;
            __syncthreads();
            for (int st = 64; st > 0; st >>= 1) {
                if (tid < st) {
                    float w2 = redv[tid + st];
                    int   i2 = redi[tid + st];
                    if (w2 > redv[tid] || (w2 == redv[tid] && i2 < redi[tid])) {
                        redv[tid] = w2;
                        redi[tid] = i2;
                    }
                }
                __syncthreads();
            }
            float m = redv[0];
            int amax = redi[0];
            __syncthreads();

            float e[4], lsum = 0.f;
            #pragma unroll
            for (int q = 0; q < 4; q++) {
                e[q] = expf(v[q] - m);
                lsum += e[q];
            }
            redv[tid] = lsum;
            __syncthreads();
            for (int st = 64; st > 0; st >>= 1) {
                if (tid < st) redv[tid] += redv[tid + st];
                __syncthreads();
            }
            float inv = 1.f / redv[0];

            float* orow = out + (size_t)b * Lsz * Vsz + (size_t)t * Vsz;
            #pragma unroll
            for (int q = 0; q < 4; q++) {
                int s = tid + 128 * q;
                if (s < len)
                    atomicAdd(&orow[uttrs[b * Ssz + s]], e[q] * inv);
            }

            if (tid == 0) {
                int pred = uttrs[b * Ssz + amax];
                if (write_preds)
                    out[(size_t)Bsz * Lsz * Vsz + (size_t)t * Bsz + b] = (float)pred;
                int nxt = tf ? targets[b * Lsz + t] : pred;
                ((int*)flg)[1] = nxt;
            }
            __syncthreads();
            int nxt = ((int*)flg)[1];
            if (tid < 100)
                ((float4*)(g_x + b * Hsz))[tid] =
                    ((const float4*)(emb + (size_t)nxt * Hsz))[tid];

            block_arrive(&g_fusedCnt[t]);
        }
    }
}

// ---------------- launch ----------------
extern "C" void kernel_launch(void* const* d_in, const int* in_sizes, int n_in,
                              void* d_out, int out_size) {
    const float* eh       = (const float*)d_in[0];
    const float* enc      = (const float*)d_in[1];
    const int*   lens     = (const int*)d_in[2];
    const int*   uttrs    = (const int*)d_in[3];
    const int*   targets  = (const int*)d_in[4];
    const int*   slot     = (const int*)d_in[5];
    const int*   use_tf   = (const int*)d_in[6];
    const float* emb      = (const float*)d_in[7];
    const float* slot_emb = (const float*)d_in[8];
    const float* Wih      = (const float*)d_in[9];
    const float* Whh      = (const float*)d_in[10];
    const float* bih      = (const float*)d_in[11];
    const float* bhh      = (const float*)d_in[12];
    float* out = (float*)d_out;

    int write_preds = out_size > Bsz * Lsz * Vsz;
    reset_kernel<<<1, 128>>>();
    persist_kernel<<<NBLK, NTHR>>>(eh, enc, lens, uttrs, targets, slot, use_tf,
                                   emb, slot_emb, Wih, Whh, bih, bhh,
                                   out, out_size, write_preds);
}